// round 7
// baseline (speedup 1.0000x reference)
#include <cuda_runtime.h>

#define KSEL 512
#define SPLITS 8
#define BLOCK 512
#define NBLK 128                  // all blocks are symmetric workers
#define NBINS 2048                // 11-bit histogram
#define SHIFT1 21
#define BCAP 4096                 // smem cache cap for boundary keys
#define NEG_MAX 65536
#define LN2_F 0.69314718055994530942

__device__ unsigned int g_hist[NBINS];        // zeroed by reset at end of each run
__device__ unsigned int g_boundary[NEG_MAX];
__device__ float g_E[KSEL];
__device__ float g_partials[NBLK];
__device__ int g_cnt1 = 0, g_cnt2 = 0, g_cnt3 = 0;
__device__ volatile int g_go1 = 0, g_go2 = 0;
__device__ unsigned int g_cgt = 0, g_mcnt = 0;

__device__ __forceinline__ unsigned int f2key(float x) {
    unsigned int u = __float_as_uint(x);
    return (u & 0x80000000u) ? ~u : (u | 0x80000000u);  // order-preserving
}
__device__ __forceinline__ float key2f(unsigned int k) {
    unsigned int u = (k & 0x80000000u) ? (k ^ 0x80000000u) : ~k;
    return __uint_as_float(u);
}

// Blackwell packed f32x2 (PTX-only): 2 flops per fma-pipe issue slot
__device__ __forceinline__ unsigned long long ffma2(unsigned long long a,
                                                    unsigned long long b,
                                                    unsigned long long c) {
    unsigned long long d;
    asm("fma.rn.f32x2 %0, %1, %2, %3;" : "=l"(d) : "l"(a), "l"(b), "l"(c));
    return d;
}
__device__ __forceinline__ unsigned long long fmul2(unsigned long long a,
                                                    unsigned long long b) {
    unsigned long long d;
    asm("mul.rn.f32x2 %0, %1, %2;" : "=l"(d) : "l"(a), "l"(b));
    return d;
}
__device__ __forceinline__ unsigned long long pack2(float lo, float hi) {
    unsigned long long d;
    asm("mov.b64 %0, {%1, %2};" : "=l"(d) : "f"(lo), "f"(hi));
    return d;
}
__device__ __forceinline__ void unpack2(unsigned long long v, float& lo, float& hi) {
    asm("mov.b64 {%0, %1}, %2;" : "=f"(lo), "=f"(hi) : "l"(v));
}

__global__ void __launch_bounds__(BLOCK, 1)
pauc_kernel(const float* __restrict__ neg, int n_neg,
            const float* __restrict__ pos, int n_pos,
            float* __restrict__ out, float final_scale, int kpb)
{
    __shared__ float sE[KSEL] __attribute__((aligned(16)));
    __shared__ unsigned int sbound[BCAP];
    __shared__ unsigned int sh_bstar, sh_C1, sh_rem;
    __shared__ int sh_last;
    __shared__ float sh_red[BLOCK / 32];

    const int tid = threadIdx.x;
    const int lane = tid & 31;
    const int b = blockIdx.x;

    // ---------- phase 0: load own key + histogram + F (all parallel) ----------
    const int gk = b * kpb + tid;
    const bool has = (tid < kpb) && (gk < n_neg);
    unsigned int key = 0u;
    if (has) {
        key = f2key(__ldg(&neg[gk]));
        atomicAdd(&g_hist[key >> SHIFT1], 1u);      // REDG, ~8 collisions/address
    }

    const int t = b * BLOCK + tid;                  // main-task id
    const int s = t / n_pos;                        // split id
    const int i = t - s * n_pos;                    // pos row
    const bool valid = (s < SPLITS);
    float F = 0.0f;
    if (valid) F = __expf(-__ldg(&pos[i]));

    // ---------- grid barrier 1 ----------
    __threadfence();
    __syncthreads();
    if (tid == 0) {
        if (atomicAdd(&g_cnt1, 1) == NBLK - 1) g_go1 = 1;
        else while (g_go1 == 0) __nanosleep(32);
        __threadfence();
    }
    __syncthreads();

    // ---------- phase 1: redundant scan of 2048-bin histogram (warp 0) ----------
    if (tid < 32) {
        unsigned int sum = 0u;
        #pragma unroll
        for (int j = 0; j < 64; j++) sum += g_hist[tid * 64 + j];   // L2 broadcast
        unsigned int incl = sum;                    // suffix over this+higher chunks
        #pragma unroll
        for (int off = 1; off < 32; off <<= 1) {
            const unsigned int v = __shfl_down_sync(0xffffffffu, incl, off);
            if (tid + off < 32) incl += v;
        }
        const unsigned int excl = incl - sum;       // count strictly above chunk
        if (excl < KSEL && KSEL <= incl) {          // exactly one lane
            unsigned int cum = excl;
            for (int j = 63; j >= 0; j--) {
                const unsigned int nb = g_hist[tid * 64 + j];
                if (cum + nb >= KSEL) {
                    sh_bstar = (unsigned int)(tid * 64 + j);
                    sh_C1 = cum;                    // exact count above bin b*
                    sh_rem = KSEL - cum;            // needed from inside b*
                    break;
                }
                cum += nb;
            }
        }
    }
    __syncthreads();
    const unsigned int bs = sh_bstar, C1 = sh_C1, rem = sh_rem;

    // ---------- phase 2: classify own key (warp-aggregated global slots) ----------
    {
        const unsigned int bin = key >> SHIFT1;
        const bool gt = has && (bin > bs);
        const bool eq = has && (bin == bs);
        const unsigned int bgt = __ballot_sync(0xffffffffu, gt);
        const unsigned int beq = __ballot_sync(0xffffffffu, eq);
        if (bgt) {
            const int leader = __ffs(bgt) - 1;
            unsigned int base;
            if (lane == leader) base = atomicAdd(&g_cgt, (unsigned int)__popc(bgt));
            base = __shfl_sync(0xffffffffu, base, leader);
            if (gt) g_E[base + __popc(bgt & ((1u << lane) - 1u))] = __expf(key2f(key));
        }
        if (beq) {
            const int leader = __ffs(beq) - 1;
            unsigned int base;
            if (lane == leader) base = atomicAdd(&g_mcnt, (unsigned int)__popc(beq));
            base = __shfl_sync(0xffffffffu, base, leader);
            if (eq) g_boundary[base + __popc(beq & ((1u << lane) - 1u))] = key;
        }
    }

    // ---------- grid barrier 2 ----------
    __threadfence();
    __syncthreads();
    if (tid == 0) {
        if (atomicAdd(&g_cnt2, 1) == NBLK - 1) g_go2 = 1;
        else while (g_go2 == 0) __nanosleep(32);
        __threadfence();
    }
    __syncthreads();

    // ---------- phase 3: build sE; resolve boundary locally (O(m^2) ranks) ----------
    for (int j = tid; j < (int)C1; j += BLOCK) sE[j] = g_E[j];
    const unsigned int m = *(volatile unsigned int*)&g_mcnt;
    const bool cached = (m <= BCAP);
    if (cached)
        for (unsigned int j = tid; j < m; j += BLOCK) sbound[j] = g_boundary[j];
    __syncthreads();
    for (unsigned int bi = tid; bi < m; bi += BLOCK) {
        const unsigned int k = cached ? sbound[bi] : g_boundary[bi];
        unsigned int rank = 0u;
        for (unsigned int j = 0; j < m; j++) {
            const unsigned int kj = cached ? sbound[j] : g_boundary[j];
            rank += (kj > k) || (kj == k && j < bi);   // total order: exact
        }
        if (rank < rem) sE[C1 + rank] = __expf(key2f(k));
    }
    __syncthreads();

    // ---------- phase 4: main compute (f32x2 packed, log2 accumulation) ----------
    float acc = 0.0f;
    if (valid) {
        const unsigned long long FF   = pack2(F, F);
        const unsigned long long ones = pack2(1.0f, 1.0f);
        const unsigned long long* e2 =
            reinterpret_cast<const unsigned long long*>(&sE[s * (KSEL / SPLITS)]);
        #pragma unroll
        for (int g = 0; g < 4; g++) {               // 4 groups x 8 pairs = 64 negs
            unsigned long long pp = ffma2(e2[g * 8], FF, ones);
            #pragma unroll
            for (int q = 1; q < 8; q++)
                pp = fmul2(pp, ffma2(e2[g * 8 + q], FF, ones));
            float plo, phi;
            unpack2(pp, plo, phi);
            acc += __log2f(plo);
            acc += __log2f(phi);
        }
    }
    #pragma unroll
    for (int off = 16; off > 0; off >>= 1)
        acc += __shfl_down_sync(0xffffffffu, acc, off);
    if (lane == 0) sh_red[tid >> 5] = acc;
    __syncthreads();

    // ---------- phase 5: partial -> ticket; last block finalizes + resets ----------
    if (tid == 0) {
        float a = 0.0f;
        #pragma unroll
        for (int w = 0; w < BLOCK / 32; w++) a += sh_red[w];
        g_partials[b] = a;
        __threadfence();
        sh_last = (atomicAdd(&g_cnt3, 1) == NBLK - 1) ? 1 : 0;
    }
    __syncthreads();
    if (sh_last) {
        if (tid == 0) __threadfence();              // acquire all partials
        __syncthreads();
        if (tid < 32) {
            float a = 0.0f;
            #pragma unroll
            for (int j = 0; j < NBLK / 32; j++) a += g_partials[j * 32 + tid];
            #pragma unroll
            for (int off = 16; off > 0; off >>= 1)
                a += __shfl_down_sync(0xffffffffu, a, off);
            if (tid == 0) out[0] = a * final_scale; // ln2 * inv_denom
        }
        // reset device state for graph replay (stream-ordered vs next launch)
        for (int j = tid; j < NBINS; j += BLOCK) g_hist[j] = 0u;
        if (tid == 0) {
            g_cnt1 = 0; g_cnt2 = 0; g_cnt3 = 0;
            g_go1 = 0; g_go2 = 0;
            g_cgt = 0u; g_mcnt = 0u;
        }
    }
}

// ---------------------------------------------------------------------------
extern "C" void kernel_launch(void* const* d_in, const int* in_sizes, int n_in,
                              void* d_out, int out_size) {
    const float* neg = (const float*)d_in[0];   // score_neg [16384]
    const float* pos = (const float*)d_in[1];   // score_pos [8192]
    const int n_neg = in_sizes[0];
    const int n_pos = in_sizes[1];

    const int kpb = (n_neg + NBLK - 1) / NBLK;              // 128 keys per block
    const float final_scale =
        (float)(LN2_F / ((double)n_neg * (double)n_pos));   // ln2 * inv_denom

    pauc_kernel<<<NBLK, BLOCK>>>(neg, n_neg, pos, n_pos,
                                 (float*)d_out, final_scale, kpb);
}

// round 8
// speedup vs baseline: 1.1357x; 1.1357x over previous
#include <cuda_runtime.h>

#define KSEL 512
#define BLOCK 512
#define NBLK 128
#define NBINS 2048                // 11-bit histogram (sign+exp+2 mantissa bits)
#define SHIFT1 21
#define KPT 32                    // 512*32 = 16384 keys
#define BCAP 2048                 // smem boundary buffer (expected m ~ 300)
#define LN2_F 0.69314718055994530942

__device__ float g_partials[NBLK];
__device__ int g_ticket = 0;      // reset by last block each run (graph-safe)

__device__ __forceinline__ unsigned int f2key(float x) {
    unsigned int u = __float_as_uint(x);
    return (u & 0x80000000u) ? ~u : (u | 0x80000000u);  // order-preserving
}
__device__ __forceinline__ float key2f(unsigned int k) {
    unsigned int u = (k & 0x80000000u) ? (k ^ 0x80000000u) : ~k;
    return __uint_as_float(u);
}

// Blackwell packed f32x2 (PTX-only): 2 flops per fma-pipe issue slot
__device__ __forceinline__ unsigned long long ffma2(unsigned long long a,
                                                    unsigned long long b,
                                                    unsigned long long c) {
    unsigned long long d;
    asm("fma.rn.f32x2 %0, %1, %2, %3;" : "=l"(d) : "l"(a), "l"(b), "l"(c));
    return d;
}
__device__ __forceinline__ unsigned long long fmul2(unsigned long long a,
                                                    unsigned long long b) {
    unsigned long long d;
    asm("mul.rn.f32x2 %0, %1, %2;" : "=l"(d) : "l"(a), "l"(b));
    return d;
}
__device__ __forceinline__ unsigned long long pack2(float lo, float hi) {
    unsigned long long d;
    asm("mov.b64 %0, {%1, %2};" : "=l"(d) : "f"(lo), "f"(hi));
    return d;
}
__device__ __forceinline__ void unpack2(unsigned long long v, float& lo, float& hi) {
    asm("mov.b64 {%0, %1}, %2;" : "=f"(lo), "=f"(hi) : "l"(v));
}

__global__ void __launch_bounds__(BLOCK, 1)
pauc_kernel(const float* __restrict__ neg, int n_neg,
            const float* __restrict__ pos, int n_pos,
            float* __restrict__ out, float final_scale, int rpb)
{
    __shared__ unsigned int hist[NBINS];                    // 8 KB
    __shared__ float sE[KSEL] __attribute__((aligned(16))); // 2 KB
    __shared__ unsigned int sbound[BCAP];                   // 8 KB
    __shared__ unsigned int sh_c1, sh_cb, sh_bstar, sh_C1, sh_rem;
    __shared__ float sh_red[BLOCK / 32];
    __shared__ int sh_last;

    const int tid = threadIdx.x;
    const int lane = tid & 31;
    const int b = blockIdx.x;

    // ---- phase 0: zero hist; load all keys (registers) + private histogram ----
    for (int j = tid; j < NBINS; j += BLOCK) hist[j] = 0u;
    if (tid == 0) { sh_c1 = 0u; sh_cb = 0u; }
    __syncthreads();

    unsigned int keys[KPT];
    #pragma unroll
    for (int c = 0; c < KPT; c++) {
        const int idx = c * BLOCK + tid;                    // coalesced
        keys[c] = (idx < n_neg) ? f2key(__ldg(&neg[idx])) : 0u;
        if (idx < n_neg) atomicAdd(&hist[keys[c] >> SHIFT1], 1u);  // spread ATOMS
    }

    // this thread's pos row (8 threads per row) — overlap MUFU with hist
    const int row = b * rpb + (tid >> 3);
    const bool rvalid = (row < n_pos) && ((tid >> 3) < rpb);
    float F = 0.0f;
    if (rvalid) F = __expf(-__ldg(&pos[row]));
    __syncthreads();

    // ---- phase 1: warp 0 scans the private histogram in smem ----
    if (tid < 32) {
        unsigned int sum = 0u;
        #pragma unroll
        for (int j = 0; j < 64; j++) sum += hist[tid * 64 + j];
        unsigned int incl = sum;                            // suffix over >= chunk
        #pragma unroll
        for (int off = 1; off < 32; off <<= 1) {
            const unsigned int v = __shfl_down_sync(0xffffffffu, incl, off);
            if (tid + off < 32) incl += v;
        }
        const unsigned int excl = incl - sum;               // strictly-above count
        if (excl < KSEL && KSEL <= incl) {                  // exactly one lane
            unsigned int cum = excl;
            for (int j = 63; j >= 0; j--) {
                const unsigned int nb = hist[tid * 64 + j];
                if (cum + nb >= KSEL) {
                    sh_bstar = (unsigned int)(tid * 64 + j);
                    sh_C1 = cum;                            // keys above bin b*
                    sh_rem = KSEL - cum;                    // taken from inside b*
                    break;
                }
                cum += nb;
            }
        }
    }
    __syncthreads();
    const unsigned int bs = sh_bstar, C1 = sh_C1, rem = sh_rem;

    // ---- phase 2: classify register keys into private sE / boundary buffer ----
    #pragma unroll
    for (int c = 0; c < KPT; c++) {
        const unsigned int k = keys[c];
        const bool in = (c * BLOCK + tid) < n_neg;
        const unsigned int bin = k >> SHIFT1;
        const bool gt = in && (bin > bs);
        const bool eq = in && (bin == bs);
        const unsigned int bgt = __ballot_sync(0xffffffffu, gt);
        const unsigned int beq = __ballot_sync(0xffffffffu, eq);
        if (bgt) {                                          // warp-aggregated slots
            const int leader = __ffs(bgt) - 1;
            unsigned int base;
            if (lane == leader) base = atomicAdd(&sh_c1, (unsigned int)__popc(bgt));
            base = __shfl_sync(0xffffffffu, base, leader);
            if (gt) sE[base + __popc(bgt & ((1u << lane) - 1u))] = __expf(key2f(k));
        }
        if (beq) {
            const int leader = __ffs(beq) - 1;
            unsigned int base;
            if (lane == leader) base = atomicAdd(&sh_cb, (unsigned int)__popc(beq));
            base = __shfl_sync(0xffffffffu, base, leader);
            if (eq) {
                const unsigned int x = base + __popc(beq & ((1u << lane) - 1u));
                if (x < BCAP) sbound[x] = k;                // m ~ 300 here
            }
        }
    }
    __syncthreads();

    // ---- phase 3: boundary bin — O(m^2) exact rank (ties bit-identical) ----
    const unsigned int m = min(sh_cb, (unsigned int)BCAP);
    for (unsigned int bi = tid; bi < m; bi += BLOCK) {
        const unsigned int k = sbound[bi];
        unsigned int rank = 0u;
        for (unsigned int j = 0; j < m; j++) {
            const unsigned int kj = sbound[j];
            rank += (kj > k) || (kj == k && j < bi);
        }
        if (rank < rem) sE[C1 + rank] = __expf(key2f(k));
    }
    __syncthreads();

    // ---- phase 4: main compute — each row summed over ALL 512 selected negs ----
    // thread sub-chunk c = tid&7 reads packed pairs j*8+c (bank-conflict-free).
    float acc = 0.0f;                                       // accumulates log2
    if (rvalid) {
        const unsigned long long FF   = pack2(F, F);
        const unsigned long long ones = pack2(1.0f, 1.0f);
        const unsigned long long* e2 = reinterpret_cast<const unsigned long long*>(sE);
        const int c = tid & 7;
        #pragma unroll
        for (int g = 0; g < 4; g++) {                       // 4 groups x 8 pairs
            unsigned long long pp = ffma2(e2[(g * 8) * 8 + c], FF, ones);
            #pragma unroll
            for (int q = 1; q < 8; q++)
                pp = fmul2(pp, ffma2(e2[(g * 8 + q) * 8 + c], FF, ones));
            float plo, phi;
            unpack2(pp, plo, phi);                          // <= ~1.4e29: no overflow
            acc += __log2f(plo);
            acc += __log2f(phi);
        }
    }

    // ---- phase 5: deterministic block reduction + last-block finalize ----
    #pragma unroll
    for (int off = 16; off > 0; off >>= 1)
        acc += __shfl_down_sync(0xffffffffu, acc, off);
    if (lane == 0) sh_red[tid >> 5] = acc;
    __syncthreads();
    if (tid == 0) {
        float a = 0.0f;
        #pragma unroll
        for (int w = 0; w < BLOCK / 32; w++) a += sh_red[w];
        g_partials[b] = a;
        __threadfence();                                    // release partial
        sh_last = (atomicAdd(&g_ticket, 1) == NBLK - 1) ? 1 : 0;
    }
    __syncthreads();
    if (sh_last) {
        if (tid == 0) __threadfence();                      // acquire partials
        __syncthreads();
        if (tid < 32) {
            float a = 0.0f;
            #pragma unroll
            for (int j = 0; j < NBLK / 32; j++) a += g_partials[j * 32 + tid];
            #pragma unroll
            for (int off = 16; off > 0; off >>= 1)
                a += __shfl_down_sync(0xffffffffu, a, off);
            if (tid == 0) {
                out[0] = a * final_scale;                   // ln2 * inv_denom
                g_ticket = 0;                               // reset for graph replay
            }
        }
    }
}

// ---------------------------------------------------------------------------
extern "C" void kernel_launch(void* const* d_in, const int* in_sizes, int n_in,
                              void* d_out, int out_size) {
    const float* neg = (const float*)d_in[0];   // score_neg [16384]
    const float* pos = (const float*)d_in[1];   // score_pos [8192]
    const int n_neg = in_sizes[0];
    const int n_pos = in_sizes[1];

    const int rpb = (n_pos + NBLK - 1) / NBLK;              // 64 rows per block
    const float final_scale =
        (float)(LN2_F / ((double)n_neg * (double)n_pos));   // ln2 * inv_denom

    pauc_kernel<<<NBLK, BLOCK>>>(neg, n_neg, pos, n_pos,
                                 (float*)d_out, final_scale, rpb);
}

// round 9
// speedup vs baseline: 1.2545x; 1.1045x over previous
#include <cuda_runtime.h>

#define KSEL 512
#define BLOCK 1024
#define NBLK 64
#define NBINS 2048                // 11-bit histogram (sign+exp+2 mantissa bits)
#define SHIFT1 21
#define KPT 16                    // 1024*16 = 16384 keys
#define BCAP 1024                 // smem boundary buffer (expected m ~ 300)
#define LN2_F 0.69314718055994530942

__device__ float g_partials[NBLK];
__device__ int g_ticket = 0;      // reset by last block each run (graph-safe)

__device__ __forceinline__ unsigned int f2key(float x) {
    unsigned int u = __float_as_uint(x);
    return (u & 0x80000000u) ? ~u : (u | 0x80000000u);  // order-preserving
}
__device__ __forceinline__ float key2f(unsigned int k) {
    unsigned int u = (k & 0x80000000u) ? (k ^ 0x80000000u) : ~k;
    return __uint_as_float(u);
}

// Blackwell packed f32x2 (PTX-only): 2 flops per fma-pipe issue slot
__device__ __forceinline__ unsigned long long ffma2(unsigned long long a,
                                                    unsigned long long b,
                                                    unsigned long long c) {
    unsigned long long d;
    asm("fma.rn.f32x2 %0, %1, %2, %3;" : "=l"(d) : "l"(a), "l"(b), "l"(c));
    return d;
}
__device__ __forceinline__ unsigned long long fmul2(unsigned long long a,
                                                    unsigned long long b) {
    unsigned long long d;
    asm("mul.rn.f32x2 %0, %1, %2;" : "=l"(d) : "l"(a), "l"(b));
    return d;
}
__device__ __forceinline__ unsigned long long pack2(float lo, float hi) {
    unsigned long long d;
    asm("mov.b64 %0, {%1, %2};" : "=l"(d) : "f"(lo), "f"(hi));
    return d;
}
__device__ __forceinline__ void unpack2(unsigned long long v, float& lo, float& hi) {
    asm("mov.b64 {%0, %1}, %2;" : "=f"(lo), "=f"(hi) : "l"(v));
}

__global__ void __launch_bounds__(BLOCK, 1)
pauc_kernel(const float* __restrict__ neg, int n_neg,
            const float* __restrict__ pos, int n_pos,
            float* __restrict__ out, float final_scale, int rpb)
{
    __shared__ unsigned int hist[NBINS];                    // 8 KB
    __shared__ float sE[KSEL] __attribute__((aligned(16))); // 2 KB
    __shared__ unsigned int sbound[BCAP];                   // 4 KB
    __shared__ unsigned int sh_c1, sh_cb, sh_bstar, sh_C1, sh_rem;
    __shared__ float sh_red[BLOCK / 32];
    __shared__ int sh_last;

    const int tid = threadIdx.x;
    const int lane = tid & 31;
    const int b = blockIdx.x;

    // ---- phase 0: zero hist; F for this thread's row; streaming histogram ----
    for (int j = tid; j < NBINS; j += BLOCK) hist[j] = 0u;
    if (tid == 0) { sh_c1 = 0u; sh_cb = 0u; }

    const int row = b * rpb + (tid >> 3);                   // 8 threads per row
    const bool rvalid = (row < n_pos) && ((tid >> 3) < rpb);
    float F = 0.0f;
    if (rvalid) F = __expf(-__ldg(&pos[row]));
    __syncthreads();

    #pragma unroll
    for (int c = 0; c < KPT; c++) {                         // streaming, no key regs
        const int idx = c * BLOCK + tid;                    // coalesced
        if (idx < n_neg)
            atomicAdd(&hist[f2key(__ldg(&neg[idx])) >> SHIFT1], 1u);  // spread ATOMS
    }
    __syncthreads();

    // ---- phase 1: warp 0 scans the private histogram in smem ----
    if (tid < 32) {
        unsigned int sum = 0u;
        #pragma unroll
        for (int j = 0; j < 64; j++) sum += hist[tid * 64 + j];
        unsigned int incl = sum;                            // suffix over >= chunk
        #pragma unroll
        for (int off = 1; off < 32; off <<= 1) {
            const unsigned int v = __shfl_down_sync(0xffffffffu, incl, off);
            if (tid + off < 32) incl += v;
        }
        const unsigned int excl = incl - sum;               // strictly-above count
        if (excl < KSEL && KSEL <= incl) {                  // exactly one lane
            unsigned int cum = excl;
            for (int j = 63; j >= 0; j--) {
                const unsigned int nb = hist[tid * 64 + j];
                if (cum + nb >= KSEL) {
                    sh_bstar = (unsigned int)(tid * 64 + j);
                    sh_C1 = cum;                            // keys above bin b*
                    sh_rem = KSEL - cum;                    // taken from inside b*
                    break;
                }
                cum += nb;
            }
        }
    }
    __syncthreads();
    const unsigned int bs = sh_bstar, C1 = sh_C1, rem = sh_rem;

    // ---- phase 2: second stream — classify into sE (gt) / sbound (eq) ----
    #pragma unroll
    for (int c = 0; c < KPT; c++) {
        const int idx = c * BLOCK + tid;
        unsigned int k = 0u;
        bool in = (idx < n_neg);
        if (in) k = f2key(__ldg(&neg[idx]));
        const unsigned int bin = k >> SHIFT1;
        const bool gt = in && (bin > bs);
        const bool eq = in && (bin == bs);
        const unsigned int bgt = __ballot_sync(0xffffffffu, gt);
        const unsigned int beq = __ballot_sync(0xffffffffu, eq);
        if (bgt) {                                          // warp-aggregated slots
            const int leader = __ffs(bgt) - 1;
            unsigned int base;
            if (lane == leader) base = atomicAdd(&sh_c1, (unsigned int)__popc(bgt));
            base = __shfl_sync(0xffffffffu, base, leader);
            if (gt) sE[base + __popc(bgt & ((1u << lane) - 1u))] = __expf(key2f(k));
        }
        if (beq) {
            const int leader = __ffs(beq) - 1;
            unsigned int base;
            if (lane == leader) base = atomicAdd(&sh_cb, (unsigned int)__popc(beq));
            base = __shfl_sync(0xffffffffu, base, leader);
            if (eq) {
                const unsigned int x = base + __popc(beq & ((1u << lane) - 1u));
                if (x < BCAP) sbound[x] = k;                // m ~ 300 expected
            }
        }
    }
    __syncthreads();

    // ---- phase 3: boundary bin — O(m^2) exact rank (ties bit-identical) ----
    const unsigned int m = min(sh_cb, (unsigned int)BCAP);
    for (unsigned int bi = tid; bi < m; bi += BLOCK) {
        const unsigned int k = sbound[bi];
        unsigned int rank = 0u;
        for (unsigned int j = 0; j < m; j++) {
            const unsigned int kj = sbound[j];
            rank += (kj > k) || (kj == k && j < bi);
        }
        if (rank < rem) sE[C1 + rank] = __expf(key2f(k));
    }
    __syncthreads();

    // ---- phase 4: main compute — 64 elems/thread over the shared sE ----
    // sub-chunk c = tid&7 reads packed pairs j*8+c: 8 addrs x 4-way bcast, no conflicts
    float acc = 0.0f;                                       // accumulates log2
    if (rvalid) {
        const unsigned long long FF   = pack2(F, F);
        const unsigned long long ones = pack2(1.0f, 1.0f);
        const unsigned long long* e2 = reinterpret_cast<const unsigned long long*>(sE);
        const int c = tid & 7;
        #pragma unroll
        for (int g = 0; g < 4; g++) {                       // 4 groups x 8 pairs
            unsigned long long pp = ffma2(e2[(g * 8) * 8 + c], FF, ones);
            #pragma unroll
            for (int q = 1; q < 8; q++)
                pp = fmul2(pp, ffma2(e2[(g * 8 + q) * 8 + c], FF, ones));
            float plo, phi;
            unpack2(pp, plo, phi);                          // <= ~3e28: no overflow
            acc += __log2f(plo);
            acc += __log2f(phi);
        }
    }

    // ---- phase 5: deterministic block reduction + last-block finalize ----
    #pragma unroll
    for (int off = 16; off > 0; off >>= 1)
        acc += __shfl_down_sync(0xffffffffu, acc, off);
    if (lane == 0) sh_red[tid >> 5] = acc;
    __syncthreads();
    if (tid == 0) {
        float a = 0.0f;
        #pragma unroll
        for (int w = 0; w < BLOCK / 32; w++) a += sh_red[w];
        g_partials[b] = a;
        __threadfence();                                    // release partial
        sh_last = (atomicAdd(&g_ticket, 1) == NBLK - 1) ? 1 : 0;
    }
    __syncthreads();
    if (sh_last) {
        if (tid == 0) __threadfence();                      // acquire partials
        __syncthreads();
        if (tid < 32) {
            float a = 0.0f;
            #pragma unroll
            for (int j = 0; j < NBLK / 32; j++) a += g_partials[j * 32 + tid];
            #pragma unroll
            for (int off = 16; off > 0; off >>= 1)
                a += __shfl_down_sync(0xffffffffu, a, off);
            if (tid == 0) {
                out[0] = a * final_scale;                   // ln2 * inv_denom
                g_ticket = 0;                               // reset for graph replay
            }
        }
    }
}

// ---------------------------------------------------------------------------
extern "C" void kernel_launch(void* const* d_in, const int* in_sizes, int n_in,
                              void* d_out, int out_size) {
    const float* neg = (const float*)d_in[0];   // score_neg [16384]
    const float* pos = (const float*)d_in[1];   // score_pos [8192]
    const int n_neg = in_sizes[0];
    const int n_pos = in_sizes[1];

    const int rpb = (n_pos + NBLK - 1) / NBLK;              // 128 rows per block
    const float final_scale =
        (float)(LN2_F / ((double)n_neg * (double)n_pos));   // ln2 * inv_denom

    pauc_kernel<<<NBLK, BLOCK>>>(neg, n_neg, pos, n_pos,
                                 (float*)d_out, final_scale, rpb);
}

// round 13
// speedup vs baseline: 1.3735x; 1.0949x over previous
#include <cuda_runtime.h>

#define KSEL 512
#define BLOCK 512
#define NBLK 128
#define NBINS 4096                // 12-bit histogram (sign+exp+3 mantissa bits)
#define SHIFT1 20
#define BCAP 2048                 // smem boundary cache (expected m ~ 145)
#define LN2_F 0.69314718055994530942

__device__ unsigned int g_hist[NBINS];       // zero-init; re-zeroed each run
__device__ unsigned int g_boundary[16384];
__device__ float g_E[KSEL];
__device__ float g_partials[NBLK];
__device__ int g_cnt1 = 0, g_cnt2 = 0, g_ticket = 0;
__device__ volatile int g_go1 = 0, g_go2 = 0;
__device__ unsigned int g_cgt = 0, g_mcnt = 0;

__device__ __forceinline__ unsigned int f2key(float x) {
    unsigned int u = __float_as_uint(x);
    return (u & 0x80000000u) ? ~u : (u | 0x80000000u);  // order-preserving
}
__device__ __forceinline__ float key2f(unsigned int k) {
    unsigned int u = (k & 0x80000000u) ? (k ^ 0x80000000u) : ~k;
    return __uint_as_float(u);
}

// Blackwell packed f32x2 (PTX-only): 2 flops per fma-pipe issue slot
__device__ __forceinline__ unsigned long long ffma2(unsigned long long a,
                                                    unsigned long long b,
                                                    unsigned long long c) {
    unsigned long long d;
    asm("fma.rn.f32x2 %0, %1, %2, %3;" : "=l"(d) : "l"(a), "l"(b), "l"(c));
    return d;
}
__device__ __forceinline__ unsigned long long fmul2(unsigned long long a,
                                                    unsigned long long b) {
    unsigned long long d;
    asm("mul.rn.f32x2 %0, %1, %2;" : "=l"(d) : "l"(a), "l"(b));
    return d;
}
__device__ __forceinline__ unsigned long long pack2(float lo, float hi) {
    unsigned long long d;
    asm("mov.b64 %0, {%1, %2};" : "=l"(d) : "f"(lo), "f"(hi));
    return d;
}
__device__ __forceinline__ void unpack2(unsigned long long v, float& lo, float& hi) {
    asm("mov.b64 {%0, %1}, %2;" : "=f"(lo), "=f"(hi) : "l"(v));
}

__global__ void __launch_bounds__(BLOCK, 1)
pauc_kernel(const float* __restrict__ neg, int n_neg,
            const float* __restrict__ pos, int n_pos,
            float* __restrict__ out, float final_scale, int kpb, int rpb)
{
    __shared__ unsigned int hist[NBINS];                    // 16 KB
    __shared__ float sE[KSEL] __attribute__((aligned(16))); // 2 KB
    __shared__ unsigned int sbound[BCAP];                   // 8 KB
    __shared__ unsigned int sh_chunk, sh_exclc, sh_bstar, sh_C1, sh_rem;
    __shared__ float sh_red[BLOCK / 32];
    __shared__ int sh_last;

    const int tid = threadIdx.x;
    const int lane = tid & 31;
    const int b = blockIdx.x;

    // ---- phase 0: own key (register) -> global hist; F for own row ----
    const bool has = (tid < kpb) && (b * kpb + tid < n_neg);
    unsigned int key = 0u;
    if (has) {
        key = f2key(__ldg(&neg[b * kpb + tid]));
        atomicAdd(&g_hist[key >> SHIFT1], 1u);              // REDG, spread bins
    }
    const int row = b * rpb + (tid >> 3);                   // 8 threads per row
    const bool rvalid = (row < n_pos) && ((tid >> 3) < rpb);
    float F = 0.0f;
    if (rvalid) F = __expf(-__ldg(&pos[row]));

    // ---- grid barrier 1 ----
    __threadfence();
    __syncthreads();
    if (tid == 0) {
        if (atomicAdd(&g_cnt1, 1) == NBLK - 1) g_go1 = 1;
        else while (g_go1 == 0) __nanosleep(32);
        __threadfence();
    }
    __syncthreads();

    // ---- phase 2: coalesced hist copy + two-level warp scan (redundant) ----
    for (int j = tid; j < NBINS; j += BLOCK) hist[j] = g_hist[j];
    __syncthreads();
    if (tid < 32) {
        // level 1: 128-bin chunks
        unsigned int sum = 0u;
        #pragma unroll
        for (int j = 0; j < NBINS / 32; j++) sum += hist[tid * (NBINS / 32) + j];
        unsigned int incl = sum;                            // suffix over >= lane
        #pragma unroll
        for (int off = 1; off < 32; off <<= 1) {
            const unsigned int v = __shfl_down_sync(0xffffffffu, incl, off);
            if (tid + off < 32) incl += v;
        }
        const unsigned int excl = incl - sum;
        if (excl < KSEL && KSEL <= incl) { sh_chunk = (unsigned int)tid; sh_exclc = excl; }
        __syncwarp();
        // level 2: 4-bin sub-chunks within the winning 128-bin chunk
        const unsigned int c = sh_chunk, exclc = sh_exclc;
        const int base = (int)c * (NBINS / 32) + tid * 4;
        unsigned int s2 = hist[base] + hist[base + 1] + hist[base + 2] + hist[base + 3];
        unsigned int incl2 = s2;
        #pragma unroll
        for (int off = 1; off < 32; off <<= 1) {
            const unsigned int v = __shfl_down_sync(0xffffffffu, incl2, off);
            if (tid + off < 32) incl2 += v;
        }
        const unsigned int above = exclc + (incl2 - s2);    // strictly above 4-bin group
        if (above < KSEL && KSEL <= above + s2) {           // exactly one lane
            unsigned int cum = above;
            #pragma unroll
            for (int j = 3; j >= 0; j--) {
                const unsigned int nb = hist[base + j];
                if (cum + nb >= KSEL) {
                    sh_bstar = (unsigned int)(base + j);
                    sh_C1 = cum;                            // keys above bin b*
                    sh_rem = KSEL - cum;                    // taken from inside b*
                    break;
                }
                cum += nb;
            }
        }
    }
    __syncthreads();
    const unsigned int bs = sh_bstar, C1 = sh_C1, rem = sh_rem;

    // ---- phase 3: classify own single key (one ballot round chip-wide) ----
    {
        const unsigned int bin = key >> SHIFT1;
        const bool gt = has && (bin > bs);
        const bool eq = has && (bin == bs);
        const unsigned int bgt = __ballot_sync(0xffffffffu, gt);
        const unsigned int beq = __ballot_sync(0xffffffffu, eq);
        if (bgt) {
            const int leader = __ffs(bgt) - 1;
            unsigned int base;
            if (lane == leader) base = atomicAdd(&g_cgt, (unsigned int)__popc(bgt));
            base = __shfl_sync(0xffffffffu, base, leader);
            if (gt) g_E[base + __popc(bgt & ((1u << lane) - 1u))] = __expf(key2f(key));
        }
        if (beq) {
            const int leader = __ffs(beq) - 1;
            unsigned int base;
            if (lane == leader) base = atomicAdd(&g_mcnt, (unsigned int)__popc(beq));
            base = __shfl_sync(0xffffffffu, base, leader);
            if (eq) g_boundary[base + __popc(beq & ((1u << lane) - 1u))] = key;
        }
    }

    // ---- grid barrier 2 ----
    __threadfence();
    __syncthreads();
    if (tid == 0) {
        if (atomicAdd(&g_cnt2, 1) == NBLK - 1) g_go2 = 1;
        else while (g_go2 == 0) __nanosleep(32);
        __threadfence();
    }
    __syncthreads();

    // hist no longer needed by anyone: zero own slice for graph replay
    for (int j = b * (NBINS / NBLK) + tid; j < (b + 1) * (NBINS / NBLK); j += BLOCK)
        g_hist[j] = 0u;

    // ---- phase 5: gather sE + redundant boundary resolution (m ~ 145) ----
    for (int j = tid; j < (int)C1; j += BLOCK) sE[j] = g_E[j];      // L2 broadcast
    const unsigned int m = min(*(volatile unsigned int*)&g_mcnt, (unsigned int)BCAP);
    for (unsigned int j = tid; j < m; j += BLOCK) sbound[j] = g_boundary[j];
    __syncthreads();
    for (unsigned int bi = tid; bi < m; bi += BLOCK) {
        const unsigned int k = sbound[bi];
        unsigned int rank = 0u;
        for (unsigned int j = 0; j < m; j++) {              // broadcast LDS
            const unsigned int kj = sbound[j];
            rank += (kj > k) || (kj == k && j < bi);        // total order: exact
        }
        if (rank < rem) sE[C1 + rank] = __expf(key2f(k));
    }
    __syncthreads();

    // ---- phase 4: main compute — 64 negs (32 pairs) per thread ----
    float acc = 0.0f;                                       // accumulates log2
    if (rvalid) {
        const unsigned long long FF   = pack2(F, F);
        const unsigned long long ones = pack2(1.0f, 1.0f);
        const unsigned long long* e2 = reinterpret_cast<const unsigned long long*>(sE);
        const int c = tid & 7;                              // bank-conflict-free
        #pragma unroll
        for (int g = 0; g < 4; g++) {                       // 4 groups x 8 pairs
            unsigned long long pp = ffma2(e2[(g * 8) * 8 + c], FF, ones);
            #pragma unroll
            for (int q = 1; q < 8; q++)
                pp = fmul2(pp, ffma2(e2[(g * 8 + q) * 8 + c], FF, ones));
            float plo, phi;
            unpack2(pp, plo, phi);                          // <= ~6e26: no overflow
            acc += __log2f(plo);
            acc += __log2f(phi);
        }
    }

    // ---- deterministic block reduction + last-block finalize ----
    #pragma unroll
    for (int off = 16; off > 0; off >>= 1)
        acc += __shfl_down_sync(0xffffffffu, acc, off);
    if (lane == 0) sh_red[tid >> 5] = acc;
    __syncthreads();
    if (tid == 0) {
        float a = 0.0f;
        #pragma unroll
        for (int w = 0; w < BLOCK / 32; w++) a += sh_red[w];
        g_partials[b] = a;
        __threadfence();                                    // release partial
        sh_last = (atomicAdd(&g_ticket, 1) == NBLK - 1) ? 1 : 0;
    }
    __syncthreads();
    if (sh_last) {
        if (tid == 0) __threadfence();                      // acquire partials
        __syncthreads();
        if (tid < 32) {
            float a = 0.0f;
            #pragma unroll
            for (int j = 0; j < NBLK / 32; j++) a += g_partials[j * 32 + tid];
            #pragma unroll
            for (int off = 16; off > 0; off >>= 1)
                a += __shfl_down_sync(0xffffffffu, a, off);
            if (tid == 0) {
                out[0] = a * final_scale;                   // ln2 * inv_denom
                // reset all sync/counter state for graph replay
                g_cnt1 = 0; g_cnt2 = 0; g_ticket = 0;
                g_go1 = 0; g_go2 = 0;
                g_cgt = 0u; g_mcnt = 0u;
            }
        }
    }
}

// ---------------------------------------------------------------------------
extern "C" void kernel_launch(void* const* d_in, const int* in_sizes, int n_in,
                              void* d_out, int out_size) {
    const float* neg = (const float*)d_in[0];   // score_neg [16384]
    const float* pos = (const float*)d_in[1];   // score_pos [8192]
    const int n_neg = in_sizes[0];
    const int n_pos = in_sizes[1];

    const int kpb = (n_neg + NBLK - 1) / NBLK;              // 128 keys per block
    const int rpb = (n_pos + NBLK - 1) / NBLK;              // 64 rows per block
    const float final_scale =
        (float)(LN2_F / ((double)n_neg * (double)n_pos));   // ln2 * inv_denom

    pauc_kernel<<<NBLK, BLOCK>>>(neg, n_neg, pos, n_pos,
                                 (float*)d_out, final_scale, kpb, rpb);
}

// round 15
// speedup vs baseline: 1.3776x; 1.0030x over previous
#include <cuda_runtime.h>

#define KSEL 512
#define BLOCK 512
#define NBLK 128
#define NBINS 4096                // 12-bit histogram (sign+exp+3 mantissa bits)
#define SHIFT1 20
#define BCAP 2048                 // smem boundary cache (expected m ~ 145)
#define NGROUP 64                 // 64 groups of 8 negs
#define LN2_F 0.69314718055994530942

__device__ unsigned int g_hist[NBINS];       // zero-init; re-zeroed each run
__device__ unsigned int g_boundary[16384];
__device__ float g_E[KSEL];
__device__ float g_partials[NBLK];
__device__ int g_cnt1 = 0, g_cnt2 = 0, g_ticket = 0;
__device__ unsigned int g_cgt = 0, g_mcnt = 0;

__device__ __forceinline__ unsigned int f2key(float x) {
    unsigned int u = __float_as_uint(x);
    return (u & 0x80000000u) ? ~u : (u | 0x80000000u);  // order-preserving
}
__device__ __forceinline__ float key2f(unsigned int k) {
    unsigned int u = (k & 0x80000000u) ? (k ^ 0x80000000u) : ~k;
    return __uint_as_float(u);
}

// Blackwell packed f32x2 (PTX-only)
__device__ __forceinline__ unsigned long long ffma2(unsigned long long a,
                                                    unsigned long long b,
                                                    unsigned long long c) {
    unsigned long long d;
    asm("fma.rn.f32x2 %0, %1, %2, %3;" : "=l"(d) : "l"(a), "l"(b), "l"(c));
    return d;
}
__device__ __forceinline__ unsigned long long pack2(float lo, float hi) {
    unsigned long long d;
    asm("mov.b64 %0, {%1, %2};" : "=l"(d) : "f"(lo), "f"(hi));
    return d;
}
__device__ __forceinline__ void unpack2(unsigned long long v, float& lo, float& hi) {
    asm("mov.b64 {%0, %1}, %2;" : "=f"(lo), "=f"(hi) : "l"(v));
}

__global__ void __launch_bounds__(BLOCK, 1)
pauc_kernel(const float* __restrict__ neg, int n_neg,
            const float* __restrict__ pos, int n_pos,
            float* __restrict__ out, float final_scale, int kpb, int rpb)
{
    __shared__ unsigned int hist[NBINS];                     // 16 KB
    __shared__ float sE[KSEL] __attribute__((aligned(16)));  // 2 KB
    __shared__ unsigned int sbound[BCAP];                    // 8 KB
    __shared__ unsigned long long sC[NGROUP][9];             // packed-dup coeffs, 4.5 KB
    __shared__ float sFs[64];                                // F per row of this block
    __shared__ unsigned int sh_chunk, sh_exclc, sh_bstar, sh_C1, sh_rem;
    __shared__ float sh_red[BLOCK / 32];
    __shared__ int sh_last;

    const int tid = threadIdx.x;
    const int lane = tid & 31;
    const int b = blockIdx.x;

    // ---- phase 0: own key -> global hist; F for own rows (overlap exp) ----
    const bool has = (tid < kpb) && (b * kpb + tid < n_neg);
    unsigned int key = 0u;
    if (has) {
        key = f2key(__ldg(&neg[b * kpb + tid]));
        atomicAdd(&g_hist[key >> SHIFT1], 1u);               // REDG, spread bins
    }
    if (tid < rpb) {
        const int row = b * rpb + tid;
        sFs[tid] = (row < n_pos) ? __expf(-__ldg(&pos[row])) : 0.0f;
    }

    // ---- grid barrier 1 (tight poll on arrival counter) ----
    __threadfence();
    __syncthreads();
    if (tid == 0) {
        atomicAdd(&g_cnt1, 1);
        while (*(volatile int*)&g_cnt1 < NBLK) { }
        __threadfence();
    }
    __syncthreads();

    // ---- phase 2: coalesced hist copy + two-level warp scan (redundant) ----
    for (int j = tid; j < NBINS; j += BLOCK) hist[j] = g_hist[j];
    __syncthreads();
    if (tid < 32) {
        unsigned int sum = 0u;
        #pragma unroll
        for (int j = 0; j < NBINS / 32; j++) sum += hist[tid * (NBINS / 32) + j];
        unsigned int incl = sum;
        #pragma unroll
        for (int off = 1; off < 32; off <<= 1) {
            const unsigned int v = __shfl_down_sync(0xffffffffu, incl, off);
            if (tid + off < 32) incl += v;
        }
        const unsigned int excl = incl - sum;
        if (excl < KSEL && KSEL <= incl) { sh_chunk = (unsigned int)tid; sh_exclc = excl; }
        __syncwarp();
        const unsigned int c = sh_chunk, exclc = sh_exclc;
        const int base = (int)c * (NBINS / 32) + tid * 4;
        unsigned int s2 = hist[base] + hist[base + 1] + hist[base + 2] + hist[base + 3];
        unsigned int incl2 = s2;
        #pragma unroll
        for (int off = 1; off < 32; off <<= 1) {
            const unsigned int v = __shfl_down_sync(0xffffffffu, incl2, off);
            if (tid + off < 32) incl2 += v;
        }
        const unsigned int above = exclc + (incl2 - s2);
        if (above < KSEL && KSEL <= above + s2) {            // exactly one lane
            unsigned int cum = above;
            #pragma unroll
            for (int j = 3; j >= 0; j--) {
                const unsigned int nb = hist[base + j];
                if (cum + nb >= KSEL) {
                    sh_bstar = (unsigned int)(base + j);
                    sh_C1 = cum;  sh_rem = KSEL - cum;
                    break;
                }
                cum += nb;
            }
        }
    }
    __syncthreads();
    const unsigned int bs = sh_bstar, C1 = sh_C1, rem = sh_rem;

    // ---- phase 3: classify own single key (one ballot round chip-wide) ----
    {
        const unsigned int bin = key >> SHIFT1;
        const bool gt = has && (bin > bs);
        const bool eq = has && (bin == bs);
        const unsigned int bgt = __ballot_sync(0xffffffffu, gt);
        const unsigned int beq = __ballot_sync(0xffffffffu, eq);
        if (bgt) {
            const int leader = __ffs(bgt) - 1;
            unsigned int base;
            if (lane == leader) base = atomicAdd(&g_cgt, (unsigned int)__popc(bgt));
            base = __shfl_sync(0xffffffffu, base, leader);
            if (gt) g_E[base + __popc(bgt & ((1u << lane) - 1u))] = __expf(key2f(key));
        }
        if (beq) {
            const int leader = __ffs(beq) - 1;
            unsigned int base;
            if (lane == leader) base = atomicAdd(&g_mcnt, (unsigned int)__popc(beq));
            base = __shfl_sync(0xffffffffu, base, leader);
            if (eq) g_boundary[base + __popc(beq & ((1u << lane) - 1u))] = key;
        }
    }

    // ---- grid barrier 2 ----
    __threadfence();
    __syncthreads();
    if (tid == 0) {
        atomicAdd(&g_cnt2, 1);
        while (*(volatile int*)&g_cnt2 < NBLK) { }
        __threadfence();
    }
    __syncthreads();

    // zero own hist slice for graph replay (4096/128 = 32 bins per block)
    if (tid < NBINS / NBLK) g_hist[b * (NBINS / NBLK) + tid] = 0u;

    // ---- phase 5: gather sE + redundant boundary resolution (m ~ 145) ----
    for (int j = tid; j < (int)C1; j += BLOCK) sE[j] = g_E[j];       // L2 bcast
    const unsigned int m = min(*(volatile unsigned int*)&g_mcnt, (unsigned int)BCAP);
    for (unsigned int j = tid; j < m; j += BLOCK) sbound[j] = g_boundary[j];
    __syncthreads();
    for (unsigned int bi = tid; bi < m; bi += BLOCK) {
        const unsigned int k = sbound[bi];
        unsigned int rank = 0u;
        for (unsigned int j = 0; j < m; j++) {
            const unsigned int kj = sbound[j];
            rank += (kj > k) || (kj == k && j < bi);                 // exact total order
        }
        if (rank < rem) sE[C1 + rank] = __expf(key2f(k));
    }
    __syncthreads();

    // ---- phase 6: per-group elementary symmetric coefficients (redundant) ----
    // group g: prod_{j}(1 + E_j x) = sum_k e_k x^k ; all terms positive.
    if (tid < NGROUP) {
        float c[9];
        c[0] = 1.0f;
        #pragma unroll
        for (int k = 1; k < 9; k++) c[k] = 0.0f;
        #pragma unroll
        for (int j = 0; j < 8; j++) {
            const float e = sE[tid * 8 + j];
            #pragma unroll
            for (int k = 8; k >= 1; k--) c[k] = __fmaf_rn(e, c[k - 1], c[k]);
        }
        #pragma unroll
        for (int k = 0; k < 9; k++) sC[tid][k] = pack2(c[k], c[k]);  // dup lanes
    }
    __syncthreads();

    // ---- phase 4: main compute — Horner over groups, 2 rows packed ----
    // thread: row-pair rp = tid>>4 (rows b*64+rp, +32), groups c4+16*gi (gi<4).
    const int rp = tid >> 4;
    const int c4 = tid & 15;
    const unsigned long long FF = pack2(sFs[rp], sFs[rp + 32]);
    float acc = 0.0f;                                        // accumulates log2
    #pragma unroll
    for (int gi = 0; gi < 4; gi++) {
        const int g = c4 + 16 * gi;
        unsigned long long p = sC[g][8];
        #pragma unroll
        for (int k = 7; k >= 0; k--)
            p = ffma2(p, FF, sC[g][k]);                      // P(F) = prod(1+E F)
        float plo, phi;
        unpack2(p, plo, phi);                                // <= ~1e28: no overflow
        acc += __log2f(plo);
        acc += __log2f(phi);
    }

    // ---- deterministic block reduction + last-block finalize ----
    #pragma unroll
    for (int off = 16; off > 0; off >>= 1)
        acc += __shfl_down_sync(0xffffffffu, acc, off);
    if (lane == 0) sh_red[tid >> 5] = acc;
    __syncthreads();
    if (tid == 0) {
        float a = 0.0f;
        #pragma unroll
        for (int w = 0; w < BLOCK / 32; w++) a += sh_red[w];
        g_partials[b] = a;
        __threadfence();                                     // release partial
        sh_last = (atomicAdd(&g_ticket, 1) == NBLK - 1) ? 1 : 0;
    }
    __syncthreads();
    if (sh_last) {
        if (tid == 0) __threadfence();                       // acquire partials
        __syncthreads();
        if (tid < 32) {
            float a = 0.0f;
            #pragma unroll
            for (int j = 0; j < NBLK / 32; j++) a += g_partials[j * 32 + tid];
            #pragma unroll
            for (int off = 16; off > 0; off >>= 1)
                a += __shfl_down_sync(0xffffffffu, a, off);
            if (tid == 0) {
                out[0] = a * final_scale;                    // ln2 * inv_denom
                g_cnt1 = 0; g_cnt2 = 0; g_ticket = 0;        // reset for replay
                g_cgt = 0u; g_mcnt = 0u;
            }
        }
    }
}

// ---------------------------------------------------------------------------
extern "C" void kernel_launch(void* const* d_in, const int* in_sizes, int n_in,
                              void* d_out, int out_size) {
    const float* neg = (const float*)d_in[0];   // score_neg [16384]
    const float* pos = (const float*)d_in[1];   // score_pos [8192]
    const int n_neg = in_sizes[0];
    const int n_pos = in_sizes[1];

    const int kpb = (n_neg + NBLK - 1) / NBLK;              // 128 keys per block
    const int rpb = (n_pos + NBLK - 1) / NBLK;              // 64 rows per block
    const float final_scale =
        (float)(LN2_F / ((double)n_neg * (double)n_pos));   // ln2 * inv_denom

    pauc_kernel<<<NBLK, BLOCK>>>(neg, n_neg, pos, n_pos,
                                 (float*)d_out, final_scale, kpb, rpb);
}